// round 7
// baseline (speedup 1.0000x reference)
#include <cuda_runtime.h>

#define BB 8
#define NN 512
#define PP 32
#define LL 3
#define NS 8           // n-splits for layer_z (n-chunk = 64)

typedef unsigned long long ull;

// Scratch (device globals: no allocation in kernel_launch)
__device__ float g_t31[LL][BB*NN*PP];      // [l][b][n][p]
__device__ float g_mu[BB*PP*NN];           // current layer's mu  [b][p][n]
__device__ float g_zp[NS][BB*PP*NN];       // n-split partials (+epilogue terms in ns 0)

// ---- packed f32x2 helpers (sm_100+) ---------------------------------------
__device__ __forceinline__ ull pk(float lo, float hi) {
    ull r; asm("mov.b64 %0,{%1,%2};" : "=l"(r) : "f"(lo), "f"(hi)); return r;
}
__device__ __forceinline__ void upk(ull v, float& lo, float& hi) {
    asm("mov.b64 {%0,%1},%2;" : "=f"(lo), "=f"(hi) : "l"(v));
}
__device__ __forceinline__ ull fma2(ull a, ull b, ull c) {
    ull d; asm("fma.rn.f32x2 %0,%1,%2,%3;" : "=l"(d) : "l"(a), "l"(b), "l"(c));
    return d;
}
__device__ __forceinline__ ull add2(ull a, ull b) {
    ull d; asm("add.rn.f32x2 %0,%1,%2;" : "=l"(d) : "l"(a), "l"(b));
    return d;
}

union F4U2 { float4 f4; ull u2[2]; };

// ---- cp.async helpers ------------------------------------------------------
__device__ __forceinline__ void cp16(void* smem_dst, const void* gsrc) {
    unsigned d = (unsigned)__cvta_generic_to_shared(smem_dst);
    asm volatile("cp.async.ca.shared.global [%0], [%1], 16;"
                 :: "r"(d), "l"(gsrc));
}
__device__ __forceinline__ void cp_commit() {
    asm volatile("cp.async.commit_group;");
}
template <int N>
__device__ __forceinline__ void cp_wait() {
    asm volatile("cp.async.wait_group %0;" :: "n"(N));
}

// ---------------------------------------------------------------------------
// K1 (fused over layers): t31[l][b][n][p] = sum_m relu(A + B*w + C*s)
//   = 0.5*(Sum v + Sum|v|);  Sum v closed-form via row sums.
// grid (N, B), block 256. lane = p; 8 warps split m; 3 layers interleaved.
// ---------------------------------------------------------------------------
__global__ __launch_bounds__(256) void edge_kernel(
    const float* __restrict__ x, const float* __restrict__ wgt,
    const float* __restrict__ t4)
{
    __shared__ float w_s[NN];
    __shared__ float s_s[NN];
    __shared__ float red_s[LL][8][PP];
    __shared__ float rw_s[8], rs_s[8];

    int n = blockIdx.x, b = blockIdx.y;
    int tid = threadIdx.x;
    int lane = tid & 31;
    int wid  = tid >> 5;

    const float* wrow = wgt + ((size_t)(b * NN + n)) * NN;
    const float* xb   = x + b * NN;

    float pw = 0.f, ps = 0.f;
    for (int m = tid; m < NN; m += 256) {
        float w = wrow[m];
        float s = 2.0f * xb[m] - 1.0f;
        w_s[m] = w;
        s_s[m] = s;
        pw += w;
        ps += s;
    }
    #pragma unroll
    for (int o = 16; o; o >>= 1) {
        pw += __shfl_xor_sync(0xffffffffu, pw, o);
        ps += __shfl_xor_sync(0xffffffffu, ps, o);
    }
    if (lane == 0) { rw_s[wid] = pw; rs_s[wid] = ps; }

    float xn = xb[n];
    float sn = 2.0f * xn - 1.0f;

    float As[LL], Bs[LL], Cs[LL];
    ull A2[LL], B2[LL], C2[LL];
    #pragma unroll
    for (int l = 0; l < LL; l++) {
        const float* t4p = t4 + (l * PP + lane) * 4;
        float c0 = t4p[0], c1 = t4p[1], c2 = t4p[2], c3 = t4p[3];
        float A  = fmaf(c0, xn, fmaf(0.5f, c2, c3));
        float C  = -0.5f * c2 * sn;
        As[l] = A; Bs[l] = c1; Cs[l] = C;
        A2[l] = pk(A, A);
        B2[l] = pk(c1, c1);
        C2[l] = pk(C, C);
    }

    __syncthreads();

    float sw = 0.f, ss = 0.f;
    #pragma unroll
    for (int k = 0; k < 8; k++) { sw += rw_s[k]; ss += rs_s[k]; }

    const ull ABSM = 0x7fffffff7fffffffULL;
    ull sa[LL] = {0, 0, 0};   // packed sum of |v|

    int m0 = wid * (NN / 8);
    #pragma unroll 4
    for (int m = m0; m < m0 + NN / 8; m += 4) {
        F4U2 w4, s4;
        w4.f4 = *(const float4*)(w_s + m);
        s4.f4 = *(const float4*)(s_s + m);
        #pragma unroll
        for (int l = 0; l < LL; l++) {
            ull v0 = fma2(C2[l], s4.u2[0], fma2(B2[l], w4.u2[0], A2[l]));
            ull v1 = fma2(C2[l], s4.u2[1], fma2(B2[l], w4.u2[1], A2[l]));
            sa[l] = add2(sa[l], add2(v0 & ABSM, v1 & ABSM));
        }
    }

    #pragma unroll
    for (int l = 0; l < LL; l++) {
        float a, bb;
        upk(sa[l], a, bb);
        red_s[l][wid][lane] = a + bb;
    }
    __syncthreads();

    if (wid < LL) {
        int l = wid;
        float stot = red_s[l][0][lane];
        #pragma unroll
        for (int k = 1; k < 8; k++) stot += red_s[l][k][lane];
        float sv = fmaf(512.0f, As[l], fmaf(Bs[l], sw, Cs[l] * ss));
        g_t31[l][(b * NN + n) * PP + lane] = 0.5f * (sv + stot);
    }
}

// ---------------------------------------------------------------------------
// K2 (per layer l>=1): partial z over n-chunk, nu computed on the fly.
//   nu[p][n] = sum_k t2[l][p][k] * mu[k][n]        (32x64 chunk, in smem)
//   zp[p][j] = sum_{n in chunk} nu[p][n]*adj[b][n][j]  (registers: 4p x 4j)
//   ns==0 blocks also add term1 + t3[l] @ t31[l].
// grid (4, B, NS), block 256. warp w: p = 4w..4w+3; lane: j = j0+lane*4..+3.
// ---------------------------------------------------------------------------
__global__ __launch_bounds__(256) void layer_z_kernel(
    const float* __restrict__ x, const float* __restrict__ extra,
    const float* __restrict__ adj,
    const float* __restrict__ t1, const float* __restrict__ t2,
    const float* __restrict__ t3, int layer)
{
    // region1: adj double buffer (2*16*128 = 4096 floats)
    //          OR t31 tile (128*33 = 4224 floats)  -> size to the max + pad
    __shared__ float r1[4352];
    // region2: mu chunk (32*64 = 2048) OR t3^T (32*36 = 1152)
    __shared__ float r2[2048];
    __shared__ float nu_s[64][36];     // [nn][p]
    __shared__ float t2_s[PP][33];     // [p][k]

    float (*a_s)[16][128] = (float (*)[16][128])r1;
    float (*t31_s)[33]    = (float (*)[33])r1;
    float (*mu_s)[64]     = (float (*)[64])r2;
    float (*t3t_s)[36]    = (float (*)[36])r2;

    int jt = blockIdx.x, b = blockIdx.y, ns = blockIdx.z;
    int tid  = threadIdx.x;
    int lane = tid & 31;
    int w    = tid >> 5;
    int j0   = jt * 128;
    int n0   = ns * 64;

    // kick off adj sub-tile 0 early
    {
        #pragma unroll
        for (int pass = 0; pass < 2; pass++) {
            int i = tid + pass * 256;
            int row = i >> 5, col4 = (i & 31) * 4;
            cp16(&a_s[0][row][col4],
                 adj + ((size_t)(b * NN + n0 + row)) * NN + j0 + col4);
        }
        cp_commit();
    }

    // stage t2[layer] and mu chunk
    #pragma unroll
    for (int pass = 0; pass < 4; pass++) {
        int idx = tid + pass * 256;          // p*32+k
        t2_s[idx >> 5][idx & 31] = t2[layer * PP * PP + idx];
    }
    #pragma unroll
    for (int pass = 0; pass < 2; pass++) {
        int i = tid + pass * 256;            // 0..511
        int k = i >> 4, nn4 = (i & 15) * 4;
        *(float4*)&mu_s[k][nn4] =
            *(const float4*)(g_mu + ((size_t)b * PP + k) * NN + n0 + nn4);
    }
    __syncthreads();

    // nu_s[nn][p] = sum_k t2_s[p][k] * mu_s[k][nn]
    {
        int p  = tid >> 3;
        int n8 = tid & 7;
        #pragma unroll
        for (int it = 0; it < 8; it++) {
            int nn = it * 8 + n8;
            float acc = 0.0f;
            #pragma unroll
            for (int k = 0; k < PP; k++)
                acc = fmaf(t2_s[p][k], mu_s[k][nn], acc);
            nu_s[nn][p] = acc;
        }
    }
    __syncthreads();

    // main loop over 4 adj sub-tiles of 16 n
    float4 acc[4];
    #pragma unroll
    for (int i = 0; i < 4; i++) acc[i] = make_float4(0.f, 0.f, 0.f, 0.f);

    #pragma unroll
    for (int t = 0; t < 4; t++) {
        if (t < 3) {
            #pragma unroll
            for (int pass = 0; pass < 2; pass++) {
                int i = tid + pass * 256;
                int row = i >> 5, col4 = (i & 31) * 4;
                cp16(&a_s[(t + 1) & 1][row][col4],
                     adj + ((size_t)(b * NN + n0 + (t + 1) * 16 + row)) * NN + j0 + col4);
            }
            cp_commit();
            cp_wait<1>();
        } else {
            cp_wait<0>();
        }
        __syncthreads();

        int buf = t & 1;
        #pragma unroll
        for (int nn = 0; nn < 16; nn++) {
            float4 a4 = *(const float4*)&a_s[buf][nn][lane * 4];
            float4 p4 = *(const float4*)&nu_s[t * 16 + nn][w * 4];
            acc[0].x = fmaf(p4.x, a4.x, acc[0].x);
            acc[0].y = fmaf(p4.x, a4.y, acc[0].y);
            acc[0].z = fmaf(p4.x, a4.z, acc[0].z);
            acc[0].w = fmaf(p4.x, a4.w, acc[0].w);
            acc[1].x = fmaf(p4.y, a4.x, acc[1].x);
            acc[1].y = fmaf(p4.y, a4.y, acc[1].y);
            acc[1].z = fmaf(p4.y, a4.z, acc[1].z);
            acc[1].w = fmaf(p4.y, a4.w, acc[1].w);
            acc[2].x = fmaf(p4.z, a4.x, acc[2].x);
            acc[2].y = fmaf(p4.z, a4.y, acc[2].y);
            acc[2].z = fmaf(p4.z, a4.z, acc[2].z);
            acc[2].w = fmaf(p4.z, a4.w, acc[2].w);
            acc[3].x = fmaf(p4.w, a4.x, acc[3].x);
            acc[3].y = fmaf(p4.w, a4.y, acc[3].y);
            acc[3].z = fmaf(p4.w, a4.z, acc[3].z);
            acc[3].w = fmaf(p4.w, a4.w, acc[3].w);
        }
        __syncthreads();
    }

    // ns==0: add term1 + t3 @ t31 into acc
    if (ns == 0) {
        // restage (reuses r1 / r2 regions; r1 sized for t31_s)
        #pragma unroll
        for (int pass = 0; pass < 16; pass++) {
            int idx = tid + pass * 256;       // jl*32 + q
            int jl = idx >> 5, q = idx & 31;
            t31_s[jl][q] = g_t31[layer][((size_t)b * NN + j0 + jl) * PP + q];
        }
        #pragma unroll
        for (int pass = 0; pass < 4; pass++) {
            int idx = tid + pass * 256;       // p*32+q
            t3t_s[idx & 31][idx >> 5] = t3[layer * PP * PP + idx];
        }
        __syncthreads();

        float4 x4 = *(const float4*)(x + b * NN + j0 + lane * 4);
        float4 e4 = *(const float4*)(extra + b * NN + j0 + lane * 4);
        const float xs[4] = {x4.x, x4.y, x4.z, x4.w};
        const float es[4] = {e4.x, e4.y, e4.z, e4.w};

        float* accf = (float*)acc;    // acc[i] = p row i, components = j
        #pragma unroll
        for (int i = 0; i < 4; i++) {
            const float* t1p = t1 + (layer * PP + w * 4 + i) * 3;
            float c0 = t1p[0], c1 = t1p[1], c2 = t1p[2];
            #pragma unroll
            for (int jj = 0; jj < 4; jj++)
                accf[i * 4 + jj] += fmaf(c0, 1.0f - xs[jj], fmaf(c2, es[jj], c1));
        }
        #pragma unroll
        for (int q = 0; q < PP; q++) {
            float4 t3q = *(const float4*)&t3t_s[q][w * 4];   // t3[p][q], 4 p
            const float t3s[4] = {t3q.x, t3q.y, t3q.z, t3q.w};
            #pragma unroll
            for (int jj = 0; jj < 4; jj++) {
                float tv = t31_s[lane * 4 + jj][q];
                #pragma unroll
                for (int i = 0; i < 4; i++)
                    accf[i * 4 + jj] = fmaf(t3s[i], tv, accf[i * 4 + jj]);
            }
        }
    }

    float* gz = g_zp[ns] + ((size_t)(b * PP + w * 4)) * NN + j0 + lane * 4;
    #pragma unroll
    for (int i = 0; i < 4; i++)
        *(float4*)(gz + (size_t)i * NN) = acc[i];
}

// ---------------------------------------------------------------------------
// K3: mu = relu(sum_ns zp[ns]) -> g_mu (dst=0) or out (dst=1). Elementwise.
// grid 128, block 256, float4 per thread.
// ---------------------------------------------------------------------------
__global__ __launch_bounds__(256) void merge_kernel(int dst, float* __restrict__ out)
{
    int idx = (blockIdx.x * 256 + threadIdx.x) * 4;
    float4 s = *(const float4*)(g_zp[0] + idx);
    #pragma unroll
    for (int ns = 1; ns < NS; ns++) {
        float4 v = *(const float4*)(g_zp[ns] + idx);
        s.x += v.x; s.y += v.y; s.z += v.z; s.w += v.w;
    }
    s.x = fmaxf(s.x, 0.f); s.y = fmaxf(s.y, 0.f);
    s.z = fmaxf(s.z, 0.f); s.w = fmaxf(s.w, 0.f);
    float* o = (dst == 0) ? g_mu : out;
    *(float4*)(o + idx) = s;
}

// ---------------------------------------------------------------------------
// K4: layer 0 (mu_prev = 0): mu0 = relu(term1 + t3[0] @ t31[0]) -> g_mu
// grid (4, B), block 256. warp w: p = 4w..4w+3; lane: j = j0+lane*4..+3.
// ---------------------------------------------------------------------------
__global__ __launch_bounds__(256) void mu0_kernel(
    const float* __restrict__ x, const float* __restrict__ extra,
    const float* __restrict__ t1, const float* __restrict__ t3)
{
    __shared__ float t31_s[128][33];
    __shared__ float t3t_s[PP][36];

    int jt = blockIdx.x, b = blockIdx.y;
    int tid = threadIdx.x;
    int lane = tid & 31;
    int w = tid >> 5;
    int j0 = jt * 128;

    #pragma unroll
    for (int pass = 0; pass < 16; pass++) {
        int idx = tid + pass * 256;
        int jl = idx >> 5, q = idx & 31;
        t31_s[jl][q] = g_t31[0][((size_t)b * NN + j0 + jl) * PP + q];
    }
    #pragma unroll
    for (int pass = 0; pass < 4; pass++) {
        int idx = tid + pass * 256;
        t3t_s[idx & 31][idx >> 5] = t3[idx];
    }
    __syncthreads();

    float4 x4 = *(const float4*)(x + b * NN + j0 + lane * 4);
    float4 e4 = *(const float4*)(extra + b * NN + j0 + lane * 4);
    const float xs[4] = {x4.x, x4.y, x4.z, x4.w};
    const float es[4] = {e4.x, e4.y, e4.z, e4.w};

    float acc[4][4];
    #pragma unroll
    for (int i = 0; i < 4; i++) {
        const float* t1p = t1 + (w * 4 + i) * 3;
        float c0 = t1p[0], c1 = t1p[1], c2 = t1p[2];
        #pragma unroll
        for (int jj = 0; jj < 4; jj++)
            acc[i][jj] = fmaf(c0, 1.0f - xs[jj], fmaf(c2, es[jj], c1));
    }
    #pragma unroll
    for (int q = 0; q < PP; q++) {
        float4 t3q = *(const float4*)&t3t_s[q][w * 4];
        const float t3s[4] = {t3q.x, t3q.y, t3q.z, t3q.w};
        #pragma unroll
        for (int jj = 0; jj < 4; jj++) {
            float tv = t31_s[lane * 4 + jj][q];
            #pragma unroll
            for (int i = 0; i < 4; i++)
                acc[i][jj] = fmaf(t3s[i], tv, acc[i][jj]);
        }
    }

    #pragma unroll
    for (int i = 0; i < 4; i++) {
        float4 r;
        r.x = fmaxf(acc[i][0], 0.f);
        r.y = fmaxf(acc[i][1], 0.f);
        r.z = fmaxf(acc[i][2], 0.f);
        r.w = fmaxf(acc[i][3], 0.f);
        *(float4*)(g_mu + ((size_t)b * PP + w * 4 + i) * NN + j0 + lane * 4) = r;
    }
}

// ---------------------------------------------------------------------------
extern "C" void kernel_launch(void* const* d_in, const int* in_sizes, int n_in,
                              void* d_out, int out_size)
{
    const float* x     = (const float*)d_in[0];
    const float* adj   = (const float*)d_in[1];
    const float* wgt   = (const float*)d_in[2];
    const float* extra = (const float*)d_in[3];
    const float* t1    = (const float*)d_in[4];
    const float* t2    = (const float*)d_in[5];
    const float* t3    = (const float*)d_in[6];
    const float* t4    = (const float*)d_in[7];
    float* out = (float*)d_out;

    dim3 edge_grid(NN, BB);
    dim3 z_grid(4, BB, NS);
    dim3 mu0_grid(4, BB);

    edge_kernel<<<edge_grid, 256>>>(x, wgt, t4);
    mu0_kernel<<<mu0_grid, 256>>>(x, extra, t1, t3);

    layer_z_kernel<<<z_grid, 256>>>(x, extra, adj, t1, t2, t3, 1);
    merge_kernel<<<128, 256>>>(0, out);

    layer_z_kernel<<<z_grid, 256>>>(x, extra, adj, t1, t2, t3, 2);
    merge_kernel<<<128, 256>>>(1, out);
}

// round 8
// speedup vs baseline: 1.0288x; 1.0288x over previous
#include <cuda_runtime.h>

#define BB 8
#define NN 512
#define PP 32
#define LL 3
#define NS 16          // n-splits for layer_z (n-chunk = 32)

typedef unsigned long long ull;

// Scratch (device globals: no allocation in kernel_launch)
__device__ float g_t31[LL][BB*NN*PP];      // [l][b][n][p]
__device__ float g_mu[BB*PP*NN];           // current layer's mu  [b][p][n]
__device__ float g_zp[NS][BB*PP*NN];       // n-split partials (+epilogue terms in ns 0)

// ---- packed f32x2 helpers (sm_100+) ---------------------------------------
__device__ __forceinline__ ull pk(float lo, float hi) {
    ull r; asm("mov.b64 %0,{%1,%2};" : "=l"(r) : "f"(lo), "f"(hi)); return r;
}
__device__ __forceinline__ void upk(ull v, float& lo, float& hi) {
    asm("mov.b64 {%0,%1},%2;" : "=f"(lo), "=f"(hi) : "l"(v));
}
__device__ __forceinline__ ull fma2(ull a, ull b, ull c) {
    ull d; asm("fma.rn.f32x2 %0,%1,%2,%3;" : "=l"(d) : "l"(a), "l"(b), "l"(c));
    return d;
}
__device__ __forceinline__ ull add2(ull a, ull b) {
    ull d; asm("add.rn.f32x2 %0,%1,%2;" : "=l"(d) : "l"(a), "l"(b));
    return d;
}

union F4U2 { float4 f4; ull u2[2]; };

// ---- cp.async helpers ------------------------------------------------------
__device__ __forceinline__ void cp16(void* smem_dst, const void* gsrc) {
    unsigned d = (unsigned)__cvta_generic_to_shared(smem_dst);
    asm volatile("cp.async.ca.shared.global [%0], [%1], 16;"
                 :: "r"(d), "l"(gsrc));
}
__device__ __forceinline__ void cp_commit() {
    asm volatile("cp.async.commit_group;");
}
template <int N>
__device__ __forceinline__ void cp_wait() {
    asm volatile("cp.async.wait_group %0;" :: "n"(N));
}

// ---------------------------------------------------------------------------
// K1 (fused over layers): t31[l][b][n][p] = sum_m relu(A + B*w + C*s)
//   = 0.5*(Sum v + Sum|v|);  Sum v closed-form via row sums.
// grid (N, B), block 256. lane = p; 8 warps split m; 3 layers interleaved.
// ---------------------------------------------------------------------------
__global__ __launch_bounds__(256) void edge_kernel(
    const float* __restrict__ x, const float* __restrict__ wgt,
    const float* __restrict__ t4)
{
    __shared__ float w_s[NN];
    __shared__ float s_s[NN];
    __shared__ float red_s[LL][8][PP];
    __shared__ float rw_s[8], rs_s[8];

    int n = blockIdx.x, b = blockIdx.y;
    int tid = threadIdx.x;
    int lane = tid & 31;
    int wid  = tid >> 5;

    const float* wrow = wgt + ((size_t)(b * NN + n)) * NN;
    const float* xb   = x + b * NN;

    float pw = 0.f, ps = 0.f;
    for (int m = tid; m < NN; m += 256) {
        float w = wrow[m];
        float s = 2.0f * xb[m] - 1.0f;
        w_s[m] = w;
        s_s[m] = s;
        pw += w;
        ps += s;
    }
    #pragma unroll
    for (int o = 16; o; o >>= 1) {
        pw += __shfl_xor_sync(0xffffffffu, pw, o);
        ps += __shfl_xor_sync(0xffffffffu, ps, o);
    }
    if (lane == 0) { rw_s[wid] = pw; rs_s[wid] = ps; }

    float xn = xb[n];
    float sn = 2.0f * xn - 1.0f;

    float As[LL], Bs[LL], Cs[LL];
    ull A2[LL], B2[LL], C2[LL];
    #pragma unroll
    for (int l = 0; l < LL; l++) {
        const float* t4p = t4 + (l * PP + lane) * 4;
        float c0 = t4p[0], c1 = t4p[1], c2 = t4p[2], c3 = t4p[3];
        float A  = fmaf(c0, xn, fmaf(0.5f, c2, c3));
        float C  = -0.5f * c2 * sn;
        As[l] = A; Bs[l] = c1; Cs[l] = C;
        A2[l] = pk(A, A);
        B2[l] = pk(c1, c1);
        C2[l] = pk(C, C);
    }

    __syncthreads();

    float sw = 0.f, ss = 0.f;
    #pragma unroll
    for (int k = 0; k < 8; k++) { sw += rw_s[k]; ss += rs_s[k]; }

    const ull ABSM = 0x7fffffff7fffffffULL;
    ull sa[LL] = {0, 0, 0};   // packed sum of |v|

    int m0 = wid * (NN / 8);
    #pragma unroll 4
    for (int m = m0; m < m0 + NN / 8; m += 4) {
        F4U2 w4, s4;
        w4.f4 = *(const float4*)(w_s + m);
        s4.f4 = *(const float4*)(s_s + m);
        #pragma unroll
        for (int l = 0; l < LL; l++) {
            ull v0 = fma2(C2[l], s4.u2[0], fma2(B2[l], w4.u2[0], A2[l]));
            ull v1 = fma2(C2[l], s4.u2[1], fma2(B2[l], w4.u2[1], A2[l]));
            sa[l] = add2(sa[l], add2(v0 & ABSM, v1 & ABSM));
        }
    }

    #pragma unroll
    for (int l = 0; l < LL; l++) {
        float a, bb;
        upk(sa[l], a, bb);
        red_s[l][wid][lane] = a + bb;
    }
    __syncthreads();

    if (wid < LL) {
        int l = wid;
        float stot = red_s[l][0][lane];
        #pragma unroll
        for (int k = 1; k < 8; k++) stot += red_s[l][k][lane];
        float sv = fmaf(512.0f, As[l], fmaf(Bs[l], sw, Cs[l] * ss));
        g_t31[l][(b * NN + n) * PP + lane] = 0.5f * (sv + stot);
    }
}

// ---------------------------------------------------------------------------
// K2 (per layer l>=1): partial z over 32-n chunk, nu computed on the fly.
//   nu[p][n] = sum_k t2[l][p][k] * mu[k][n]
//   zp[p][j] = sum_{n in chunk} nu[p][n]*adj[b][n][j]   (regs: 8p x 4j)
//   ns==0 blocks also add term1 + t3[l] @ t31[l].
// grid (4, B, NS), block 128 (4 warps). warp w: p = 8w..8w+7;
// lane: j = j0 + lane*4 .. +3.  Single-staged adj (one barrier in mainloop).
// ---------------------------------------------------------------------------
__global__ __launch_bounds__(128) void layer_z_kernel(
    const float* __restrict__ x, const float* __restrict__ extra,
    const float* __restrict__ adj,
    const float* __restrict__ t1, const float* __restrict__ t2,
    const float* __restrict__ t3, int layer)
{
    // r1: adj tile (32*128 = 4096) OR t31 tile (128*33 = 4224) -> 4352
    __shared__ float r1[4352];
    // r2: mu chunk (32*32 = 1024) OR t3^T (32*36 = 1152) -> 1152
    __shared__ float r2[1152];
    __shared__ float nu_s[32][36];     // [nn][p]
    __shared__ float t2_s[PP][33];     // [p][k]

    float (*a_s)[128]  = (float (*)[128])r1;    // [nn][j]
    float (*t31_s)[33] = (float (*)[33])r1;     // [jl][q]
    float (*mu_s)[32]  = (float (*)[32])r2;     // [k][nn]
    float (*t3t_s)[36] = (float (*)[36])r2;     // [q][p]

    int jt = blockIdx.x, b = blockIdx.y, ns = blockIdx.z;
    int tid  = threadIdx.x;
    int lane = tid & 31;
    int w    = tid >> 5;               // 0..3
    int j0   = jt * 128;
    int n0   = ns * 32;

    // kick off adj tile (32 rows x 128 cols) via cp.async: 1024 cp16 / 128 thr
    {
        #pragma unroll
        for (int pass = 0; pass < 8; pass++) {
            int i = tid + pass * 128;          // 0..1023
            int row = i >> 5, col4 = (i & 31) * 4;
            cp16(&a_s[row][col4],
                 adj + ((size_t)(b * NN + n0 + row)) * NN + j0 + col4);
        }
        cp_commit();
    }

    // stage t2[layer] (32x32) and mu chunk (32k x 32n)
    #pragma unroll
    for (int pass = 0; pass < 8; pass++) {
        int idx = tid + pass * 128;            // p*32+k
        t2_s[idx >> 5][idx & 31] = t2[layer * PP * PP + idx];
    }
    #pragma unroll
    for (int pass = 0; pass < 2; pass++) {
        int i = tid + pass * 128;              // 0..255
        int k = i >> 3, nn4 = (i & 7) * 4;
        *(float4*)&mu_s[k][nn4] =
            *(const float4*)(g_mu + ((size_t)b * PP + k) * NN + n0 + nn4);
    }
    __syncthreads();

    // nu_s[nn][p] = sum_k t2_s[p][k] * mu_s[k][nn]
    // thread: p = lane, nn = w + 4*it (uniform per warp -> mu broadcast)
    {
        int p = lane;
        #pragma unroll
        for (int it = 0; it < 8; it++) {
            int nn = w + it * 4;
            float acc = 0.0f;
            #pragma unroll
            for (int k = 0; k < PP; k++)
                acc = fmaf(t2_s[p][k], mu_s[k][nn], acc);
            nu_s[nn][p] = acc;
        }
    }
    cp_wait<0>();
    __syncthreads();

    // mainloop: 32 n, no barriers. 8p x 4j accumulators.
    float4 acc[8];
    #pragma unroll
    for (int i = 0; i < 8; i++) acc[i] = make_float4(0.f, 0.f, 0.f, 0.f);

    #pragma unroll 8
    for (int nn = 0; nn < 32; nn++) {
        float4 a4 = *(const float4*)&a_s[nn][lane * 4];
        float4 p0 = *(const float4*)&nu_s[nn][w * 8];
        float4 p1 = *(const float4*)&nu_s[nn][w * 8 + 4];
        const float pq[8] = {p0.x, p0.y, p0.z, p0.w, p1.x, p1.y, p1.z, p1.w};
        #pragma unroll
        for (int i = 0; i < 8; i++) {
            acc[i].x = fmaf(pq[i], a4.x, acc[i].x);
            acc[i].y = fmaf(pq[i], a4.y, acc[i].y);
            acc[i].z = fmaf(pq[i], a4.z, acc[i].z);
            acc[i].w = fmaf(pq[i], a4.w, acc[i].w);
        }
    }

    // ns==0: add term1 + t3 @ t31 into acc (reuses r1/r2 regions)
    if (ns == 0) {
        __syncthreads();
        #pragma unroll
        for (int pass = 0; pass < 33; pass++) {
            int idx = tid + pass * 128;        // jl*32 + q, 4224 total
            if (idx < 128 * 32) {
                int jl = idx >> 5, q = idx & 31;
                t31_s[jl][q] = g_t31[layer][((size_t)b * NN + j0 + jl) * PP + q];
            }
        }
        #pragma unroll
        for (int pass = 0; pass < 8; pass++) {
            int idx = tid + pass * 128;        // p*32+q
            t3t_s[idx & 31][idx >> 5] = t3[layer * PP * PP + idx];
        }
        __syncthreads();

        float4 x4 = *(const float4*)(x + b * NN + j0 + lane * 4);
        float4 e4 = *(const float4*)(extra + b * NN + j0 + lane * 4);
        const float xs[4] = {x4.x, x4.y, x4.z, x4.w};
        const float es[4] = {e4.x, e4.y, e4.z, e4.w};

        float* accf = (float*)acc;    // acc[i] = p row i, components = j
        #pragma unroll
        for (int i = 0; i < 8; i++) {
            const float* t1p = t1 + (layer * PP + w * 8 + i) * 3;
            float c0 = t1p[0], c1 = t1p[1], c2 = t1p[2];
            #pragma unroll
            for (int jj = 0; jj < 4; jj++)
                accf[i * 4 + jj] += fmaf(c0, 1.0f - xs[jj], fmaf(c2, es[jj], c1));
        }
        #pragma unroll
        for (int q = 0; q < PP; q++) {
            float4 t3a = *(const float4*)&t3t_s[q][w * 8];     // t3[p][q], p=8w..
            float4 t3b = *(const float4*)&t3t_s[q][w * 8 + 4];
            const float t3s[8] = {t3a.x, t3a.y, t3a.z, t3a.w,
                                  t3b.x, t3b.y, t3b.z, t3b.w};
            #pragma unroll
            for (int jj = 0; jj < 4; jj++) {
                float tv = t31_s[lane * 4 + jj][q];
                #pragma unroll
                for (int i = 0; i < 8; i++)
                    accf[i * 4 + jj] = fmaf(t3s[i], tv, accf[i * 4 + jj]);
            }
        }
    }

    float* gz = g_zp[ns] + ((size_t)(b * PP + w * 8)) * NN + j0 + lane * 4;
    #pragma unroll
    for (int i = 0; i < 8; i++)
        *(float4*)(gz + (size_t)i * NN) = acc[i];
}

// ---------------------------------------------------------------------------
// K3: mu = relu(sum_ns zp[ns]) -> g_mu (dst=0) or out (dst=1). Elementwise.
// grid 256, block 128, one float4 per thread; 16 independent loads (MLP 16).
// ---------------------------------------------------------------------------
__global__ __launch_bounds__(128) void merge_kernel(int dst, float* __restrict__ out)
{
    int idx = (blockIdx.x * 128 + threadIdx.x) * 4;
    float4 v[NS];
    #pragma unroll
    for (int ns = 0; ns < NS; ns++)
        v[ns] = *(const float4*)(g_zp[ns] + idx);
    float4 s = v[0];
    #pragma unroll
    for (int ns = 1; ns < NS; ns++) {
        s.x += v[ns].x; s.y += v[ns].y; s.z += v[ns].z; s.w += v[ns].w;
    }
    s.x = fmaxf(s.x, 0.f); s.y = fmaxf(s.y, 0.f);
    s.z = fmaxf(s.z, 0.f); s.w = fmaxf(s.w, 0.f);
    float* o = (dst == 0) ? g_mu : out;
    *(float4*)(o + idx) = s;
}

// ---------------------------------------------------------------------------
// K4: layer 0 (mu_prev = 0): mu0 = relu(term1 + t3[0] @ t31[0]) -> g_mu
// grid (4, B), block 256. warp w: p = 4w..4w+3; lane: j = j0+lane*4..+3.
// ---------------------------------------------------------------------------
__global__ __launch_bounds__(256) void mu0_kernel(
    const float* __restrict__ x, const float* __restrict__ extra,
    const float* __restrict__ t1, const float* __restrict__ t3)
{
    __shared__ float t31_s[128][33];
    __shared__ float t3t_s[PP][36];

    int jt = blockIdx.x, b = blockIdx.y;
    int tid = threadIdx.x;
    int lane = tid & 31;
    int w = tid >> 5;
    int j0 = jt * 128;

    #pragma unroll
    for (int pass = 0; pass < 16; pass++) {
        int idx = tid + pass * 256;
        int jl = idx >> 5, q = idx & 31;
        t31_s[jl][q] = g_t31[0][((size_t)b * NN + j0 + jl) * PP + q];
    }
    #pragma unroll
    for (int pass = 0; pass < 4; pass++) {
        int idx = tid + pass * 256;
        t3t_s[idx & 31][idx >> 5] = t3[idx];
    }
    __syncthreads();

    float4 x4 = *(const float4*)(x + b * NN + j0 + lane * 4);
    float4 e4 = *(const float4*)(extra + b * NN + j0 + lane * 4);
    const float xs[4] = {x4.x, x4.y, x4.z, x4.w};
    const float es[4] = {e4.x, e4.y, e4.z, e4.w};

    float acc[4][4];
    #pragma unroll
    for (int i = 0; i < 4; i++) {
        const float* t1p = t1 + (w * 4 + i) * 3;
        float c0 = t1p[0], c1 = t1p[1], c2 = t1p[2];
        #pragma unroll
        for (int jj = 0; jj < 4; jj++)
            acc[i][jj] = fmaf(c0, 1.0f - xs[jj], fmaf(c2, es[jj], c1));
    }
    #pragma unroll
    for (int q = 0; q < PP; q++) {
        float4 t3q = *(const float4*)&t3t_s[q][w * 4];
        const float t3s[4] = {t3q.x, t3q.y, t3q.z, t3q.w};
        #pragma unroll
        for (int jj = 0; jj < 4; jj++) {
            float tv = t31_s[lane * 4 + jj][q];
            #pragma unroll
            for (int i = 0; i < 4; i++)
                acc[i][jj] = fmaf(t3s[i], tv, acc[i][jj]);
        }
    }

    #pragma unroll
    for (int i = 0; i < 4; i++) {
        float4 r;
        r.x = fmaxf(acc[i][0], 0.f);
        r.y = fmaxf(acc[i][1], 0.f);
        r.z = fmaxf(acc[i][2], 0.f);
        r.w = fmaxf(acc[i][3], 0.f);
        *(float4*)(g_mu + ((size_t)b * PP + w * 4 + i) * NN + j0 + lane * 4) = r;
    }
}

// ---------------------------------------------------------------------------
extern "C" void kernel_launch(void* const* d_in, const int* in_sizes, int n_in,
                              void* d_out, int out_size)
{
    const float* x     = (const float*)d_in[0];
    const float* adj   = (const float*)d_in[1];
    const float* wgt   = (const float*)d_in[2];
    const float* extra = (const float*)d_in[3];
    const float* t1    = (const float*)d_in[4];
    const float* t2    = (const float*)d_in[5];
    const float* t3    = (const float*)d_in[6];
    const float* t4    = (const float*)d_in[7];
    float* out = (float*)d_out;

    dim3 edge_grid(NN, BB);
    dim3 z_grid(4, BB, NS);
    dim3 mu0_grid(4, BB);

    edge_kernel<<<edge_grid, 256>>>(x, wgt, t4);
    mu0_kernel<<<mu0_grid, 256>>>(x, extra, t1, t3);

    layer_z_kernel<<<z_grid, 128>>>(x, extra, adj, t1, t2, t3, 1);
    merge_kernel<<<256, 128>>>(0, out);

    layer_z_kernel<<<z_grid, 128>>>(x, extra, adj, t1, t2, t3, 2);
    merge_kernel<<<256, 128>>>(1, out);
}

// round 10
// speedup vs baseline: 1.1912x; 1.1578x over previous
#include <cuda_runtime.h>

#define BB 8
#define NN 512
#define PP 32
#define LL 3

typedef unsigned long long ull;

// Scratch (device globals: no allocation in kernel_launch)
__device__ float g_t31[LL][BB*NN*PP];      // [l][b][n][p]
__device__ float g_nu[BB*NN*PP];           // TRANSPOSED: [b][n][p] = (t2[l]@mu_{l-1})[p][n]

// ---- packed f32x2 helpers (sm_100+) ---------------------------------------
__device__ __forceinline__ ull pk(float lo, float hi) {
    ull r; asm("mov.b64 %0,{%1,%2};" : "=l"(r) : "f"(lo), "f"(hi)); return r;
}
__device__ __forceinline__ void upk(ull v, float& lo, float& hi) {
    asm("mov.b64 {%0,%1},%2;" : "=f"(lo), "=f"(hi) : "l"(v));
}
__device__ __forceinline__ ull fma2(ull a, ull b, ull c) {
    ull d; asm("fma.rn.f32x2 %0,%1,%2,%3;" : "=l"(d) : "l"(a), "l"(b), "l"(c));
    return d;
}
__device__ __forceinline__ ull add2(ull a, ull b) {
    ull d; asm("add.rn.f32x2 %0,%1,%2;" : "=l"(d) : "l"(a), "l"(b));
    return d;
}

union F4U2 { float4 f4; ull u2[2]; };

// ---- cp.async helpers ------------------------------------------------------
__device__ __forceinline__ void cp16(float* smem_dst, const float* gsrc) {
    unsigned d = (unsigned)__cvta_generic_to_shared(smem_dst);
    asm volatile("cp.async.ca.shared.global [%0], [%1], 16;"
                 :: "r"(d), "l"(gsrc));
}
__device__ __forceinline__ void cp_commit() {
    asm volatile("cp.async.commit_group;");
}
template <int N>
__device__ __forceinline__ void cp_wait() {
    asm volatile("cp.async.wait_group %0;" :: "n"(N));
}

// ---------------------------------------------------------------------------
// K1 (fused over layers): t31[l][b][n][p] = sum_m relu(A + B*w + C*s)
//   = 0.5*(Sum v + Sum|v|);  Sum v closed-form via row sums.
// grid (N, B), block 256. lane = p; 8 warps split m; 3 layers interleaved.
// ---------------------------------------------------------------------------
__global__ __launch_bounds__(256) void edge_kernel(
    const float* __restrict__ x, const float* __restrict__ wgt,
    const float* __restrict__ t4)
{
    __shared__ float w_s[NN];
    __shared__ float s_s[NN];
    __shared__ float red_s[LL][8][PP];
    __shared__ float rw_s[8], rs_s[8];

    int n = blockIdx.x, b = blockIdx.y;
    int tid = threadIdx.x;
    int lane = tid & 31;
    int wid  = tid >> 5;

    const float* wrow = wgt + ((size_t)(b * NN + n)) * NN;
    const float* xb   = x + b * NN;

    float pw = 0.f, ps = 0.f;
    for (int m = tid; m < NN; m += 256) {
        float w = wrow[m];
        float s = 2.0f * xb[m] - 1.0f;
        w_s[m] = w;
        s_s[m] = s;
        pw += w;
        ps += s;
    }
    #pragma unroll
    for (int o = 16; o; o >>= 1) {
        pw += __shfl_xor_sync(0xffffffffu, pw, o);
        ps += __shfl_xor_sync(0xffffffffu, ps, o);
    }
    if (lane == 0) { rw_s[wid] = pw; rs_s[wid] = ps; }

    float xn = xb[n];
    float sn = 2.0f * xn - 1.0f;

    float As[LL], Bs[LL], Cs[LL];
    ull A2[LL], B2[LL], C2[LL];
    #pragma unroll
    for (int l = 0; l < LL; l++) {
        const float* t4p = t4 + (l * PP + lane) * 4;
        float c0 = t4p[0], c1 = t4p[1], c2 = t4p[2], c3 = t4p[3];
        float A  = fmaf(c0, xn, fmaf(0.5f, c2, c3));
        float C  = -0.5f * c2 * sn;
        As[l] = A; Bs[l] = c1; Cs[l] = C;
        A2[l] = pk(A, A);
        B2[l] = pk(c1, c1);
        C2[l] = pk(C, C);
    }

    __syncthreads();

    float sw = 0.f, ss = 0.f;
    #pragma unroll
    for (int k = 0; k < 8; k++) { sw += rw_s[k]; ss += rs_s[k]; }

    const ull ABSM = 0x7fffffff7fffffffULL;
    ull sa[LL] = {0, 0, 0};   // packed sum of |v|

    int m0 = wid * (NN / 8);
    #pragma unroll 4
    for (int m = m0; m < m0 + NN / 8; m += 4) {
        F4U2 w4, s4;
        w4.f4 = *(const float4*)(w_s + m);
        s4.f4 = *(const float4*)(s_s + m);
        #pragma unroll
        for (int l = 0; l < LL; l++) {
            ull v0 = fma2(C2[l], s4.u2[0], fma2(B2[l], w4.u2[0], A2[l]));
            ull v1 = fma2(C2[l], s4.u2[1], fma2(B2[l], w4.u2[1], A2[l]));
            sa[l] = add2(sa[l], add2(v0 & ABSM, v1 & ABSM));
        }
    }

    #pragma unroll
    for (int l = 0; l < LL; l++) {
        float a, bb;
        upk(sa[l], a, bb);
        red_s[l][wid][lane] = a + bb;
    }
    __syncthreads();

    if (wid < LL) {
        int l = wid;
        float stot = red_s[l][0][lane];
        #pragma unroll
        for (int k = 1; k < 8; k++) stot += red_s[l][k][lane];
        float sv = fmaf(512.0f, As[l], fmaf(Bs[l], sw, Cs[l] * ss));
        g_t31[l][(b * NN + n) * PP + lane] = 0.5f * (sv + stot);
    }
}

// ---------------------------------------------------------------------------
// K2 (per layer): full-n z + epilogue + next-layer nu, one block per (jt, b).
//   z[p][j]  = sum_n nu[b][n][p] * adj[b][n][j]       (has_z)
//   mu[p][j] = relu( term1 + z + sum_q t3[l][p][q]*t31[l][q][j] )
//   layer<2:  g_nu[b][j][p] = sum_q t2[l+1][p][q]*mu[q][j]
//   layer==2: out[b][p][j] = mu
// grid (16, 8), block 128. thread: pg = w + 4*(lane>>4) (p=4pg..),
//                                  jp = lane&15 (j = j0 + 2*jp, 2*jp+1)
// smem (dynamic ~145KB): adj strip [512][32], nu strip [512][32], epi tiles.
// NOTE: all float4-read tiles use stride 36 (144B, 16B-multiple) to keep
// vector loads aligned; scalar-read tiles use stride 33.
// ---------------------------------------------------------------------------
#define SM_A    0                      // a_s  [512][32]
#define SM_NU   (NN*32)                // nu_s [512][32]
#define SM_T31  (2*NN*32)              // t31_s [32][33]   (scalar reads)
#define SM_T3   (SM_T31 + 32*33)       // t3t_s [32][36]   (float4 reads)
#define SM_T2N  (SM_T3 + 32*36)        // t2n_s [32][36]   (float4 reads)
#define SM_MU   (SM_T2N + 32*36)       // mu_s  [32][33]   (scalar reads)
#define SM_TOT  (SM_MU + 32*33)        // floats

__global__ __launch_bounds__(128) void layer_kernel(
    const float* __restrict__ x, const float* __restrict__ extra,
    const float* __restrict__ adj,
    const float* __restrict__ t1, const float* __restrict__ t2,
    const float* __restrict__ t3, int layer, int has_z,
    float* __restrict__ out)
{
    extern __shared__ float sm[];
    float* a_s   = sm + SM_A;
    float* nu_s  = sm + SM_NU;
    float* t31_s = sm + SM_T31;
    float* t3t_s = sm + SM_T3;
    float* t2n_s = sm + SM_T2N;
    float* mu_s  = sm + SM_MU;

    int jt = blockIdx.x, b = blockIdx.y;
    int tid  = threadIdx.x;
    int lane = tid & 31;
    int w    = tid >> 5;
    int j0   = jt * 32;
    int pg   = w + 4 * (lane >> 4);     // 0..7, p = 4*pg..4*pg+3
    int jp   = lane & 15;               // j local = 2*jp, 2*jp+1

    float acc[4][2];
    #pragma unroll
    for (int i = 0; i < 4; i++) { acc[i][0] = 0.f; acc[i][1] = 0.f; }

    if (has_z) {
        // stage both 256-n chunks of adj + nu via cp.async (2 groups)
        #pragma unroll
        for (int c = 0; c < 2; c++) {
            #pragma unroll
            for (int pass = 0; pass < 16; pass++) {
                int i = tid + pass * 128;            // 0..2047
                int row = c * 256 + (i >> 3);
                int seg = (i & 7) * 4;
                cp16(&a_s[row * 32 + seg],
                     adj + ((size_t)(b * NN + row)) * NN + j0 + seg);
                cp16(&nu_s[row * 32 + seg],
                     g_nu + ((size_t)(b * NN + row)) * 32 + seg);
            }
            cp_commit();
        }

        cp_wait<1>();
        __syncthreads();

        #pragma unroll 8
        for (int n = 0; n < 256; n++) {
            float2 a2 = *(const float2*)&a_s[n * 32 + jp * 2];
            float4 p4 = *(const float4*)&nu_s[n * 32 + pg * 4];
            acc[0][0] = fmaf(p4.x, a2.x, acc[0][0]);
            acc[0][1] = fmaf(p4.x, a2.y, acc[0][1]);
            acc[1][0] = fmaf(p4.y, a2.x, acc[1][0]);
            acc[1][1] = fmaf(p4.y, a2.y, acc[1][1]);
            acc[2][0] = fmaf(p4.z, a2.x, acc[2][0]);
            acc[2][1] = fmaf(p4.z, a2.y, acc[2][1]);
            acc[3][0] = fmaf(p4.w, a2.x, acc[3][0]);
            acc[3][1] = fmaf(p4.w, a2.y, acc[3][1]);
        }

        cp_wait<0>();
        __syncthreads();

        #pragma unroll 8
        for (int n = 256; n < 512; n++) {
            float2 a2 = *(const float2*)&a_s[n * 32 + jp * 2];
            float4 p4 = *(const float4*)&nu_s[n * 32 + pg * 4];
            acc[0][0] = fmaf(p4.x, a2.x, acc[0][0]);
            acc[0][1] = fmaf(p4.x, a2.y, acc[0][1]);
            acc[1][0] = fmaf(p4.y, a2.x, acc[1][0]);
            acc[1][1] = fmaf(p4.y, a2.y, acc[1][1]);
            acc[2][0] = fmaf(p4.z, a2.x, acc[2][0]);
            acc[2][1] = fmaf(p4.z, a2.y, acc[2][1]);
            acc[3][0] = fmaf(p4.w, a2.x, acc[3][0]);
            acc[3][1] = fmaf(p4.w, a2.y, acc[3][1]);
        }
    }

    // stage epilogue tiles (separate smem region; one barrier)
    #pragma unroll
    for (int pass = 0; pass < 8; pass++) {
        int idx = tid + pass * 128;               // jl*32 + q
        int jl = idx >> 5, q = idx & 31;
        t31_s[jl * 33 + q] = g_t31[layer][((size_t)b * NN + j0 + jl) * PP + q];
    }
    #pragma unroll
    for (int pass = 0; pass < 8; pass++) {
        int idx = tid + pass * 128;               // p*32 + q
        int p = idx >> 5, q = idx & 31;
        t3t_s[q * 36 + p] = t3[layer * PP * PP + idx];
        if (layer < 2)
            t2n_s[q * 36 + p] = t2[(layer + 1) * PP * PP + idx];
    }
    __syncthreads();

    int jg0 = j0 + jp * 2;
    float xv0 = x[b * NN + jg0],     xv1 = x[b * NN + jg0 + 1];
    float ev0 = extra[b * NN + jg0], ev1 = extra[b * NN + jg0 + 1];

    float mu[4][2];
    #pragma unroll
    for (int i = 0; i < 4; i++) {
        const float* t1p = t1 + (layer * PP + pg * 4 + i) * 3;
        float c0 = t1p[0], c1 = t1p[1], c2 = t1p[2];
        mu[i][0] = acc[i][0] + fmaf(c0, 1.0f - xv0, fmaf(c2, ev0, c1));
        mu[i][1] = acc[i][1] + fmaf(c0, 1.0f - xv1, fmaf(c2, ev1, c1));
    }
    #pragma unroll
    for (int q = 0; q < PP; q++) {
        float4 t3v = *(const float4*)&t3t_s[q * 36 + pg * 4];
        const float t3a[4] = {t3v.x, t3v.y, t3v.z, t3v.w};
        float tv0 = t31_s[(jp * 2) * 33 + q];
        float tv1 = t31_s[(jp * 2 + 1) * 33 + q];
        #pragma unroll
        for (int i = 0; i < 4; i++) {
            mu[i][0] = fmaf(t3a[i], tv0, mu[i][0]);
            mu[i][1] = fmaf(t3a[i], tv1, mu[i][1]);
        }
    }
    #pragma unroll
    for (int i = 0; i < 4; i++) {
        mu[i][0] = fmaxf(mu[i][0], 0.0f);
        mu[i][1] = fmaxf(mu[i][1], 0.0f);
    }

    if (layer == 2) {
        #pragma unroll
        for (int i = 0; i < 4; i++) {
            float2 r = make_float2(mu[i][0], mu[i][1]);
            *(float2*)(out + ((size_t)b * PP + pg * 4 + i) * NN + jg0) = r;
        }
        return;
    }

    // mu_s[jl][q] for nu computation
    #pragma unroll
    for (int i = 0; i < 4; i++) {
        mu_s[(jp * 2) * 33 + pg * 4 + i]     = mu[i][0];
        mu_s[(jp * 2 + 1) * 33 + pg * 4 + i] = mu[i][1];
    }
    __syncthreads();

    float nu[4][2];
    #pragma unroll
    for (int i = 0; i < 4; i++) { nu[i][0] = 0.f; nu[i][1] = 0.f; }
    #pragma unroll
    for (int q = 0; q < PP; q++) {
        float4 t2v = *(const float4*)&t2n_s[q * 36 + pg * 4];
        const float t2a[4] = {t2v.x, t2v.y, t2v.z, t2v.w};
        float m0 = mu_s[(jp * 2) * 33 + q];
        float m1 = mu_s[(jp * 2 + 1) * 33 + q];
        #pragma unroll
        for (int i = 0; i < 4; i++) {
            nu[i][0] = fmaf(t2a[i], m0, nu[i][0]);
            nu[i][1] = fmaf(t2a[i], m1, nu[i][1]);
        }
    }

    // write transposed: g_nu[b][j][p], float4 over p
    float4 n0 = make_float4(nu[0][0], nu[1][0], nu[2][0], nu[3][0]);
    float4 n1 = make_float4(nu[0][1], nu[1][1], nu[2][1], nu[3][1]);
    *(float4*)(g_nu + ((size_t)b * NN + jg0) * 32 + pg * 4)       = n0;
    *(float4*)(g_nu + ((size_t)b * NN + jg0 + 1) * 32 + pg * 4)   = n1;
}

// ---------------------------------------------------------------------------
extern "C" void kernel_launch(void* const* d_in, const int* in_sizes, int n_in,
                              void* d_out, int out_size)
{
    const float* x     = (const float*)d_in[0];
    const float* adj   = (const float*)d_in[1];
    const float* wgt   = (const float*)d_in[2];
    const float* extra = (const float*)d_in[3];
    const float* t1    = (const float*)d_in[4];
    const float* t2    = (const float*)d_in[5];
    const float* t3    = (const float*)d_in[6];
    const float* t4    = (const float*)d_in[7];
    float* out = (float*)d_out;

    static const size_t smem_bytes = SM_TOT * sizeof(float);
    cudaFuncSetAttribute(layer_kernel,
                         cudaFuncAttributeMaxDynamicSharedMemorySize,
                         (int)smem_bytes);

    dim3 edge_grid(NN, BB);
    dim3 lay_grid(16, BB);

    edge_kernel<<<edge_grid, 256>>>(x, wgt, t4);

    // layer 0: no z; writes g_nu = t2[1] @ mu0 (transposed)
    layer_kernel<<<lay_grid, 128, smem_bytes>>>(x, extra, adj, t1, t2, t3, 0, 0, out);
    // layer 1: z = nu@adj; writes g_nu = t2[2] @ mu1
    layer_kernel<<<lay_grid, 128, smem_bytes>>>(x, extra, adj, t1, t2, t3, 1, 1, out);
    // layer 2: z = nu@adj; writes mu2 -> out
    layer_kernel<<<lay_grid, 128, smem_bytes>>>(x, extra, adj, t1, t2, t3, 2, 1, out);
}